// round 3
// baseline (speedup 1.0000x reference)
#include <cuda_runtime.h>
#include <cuda_bf16.h>

#define NN 50000
#define EE 800000
#define DD 64
#define LN_EPS 1e-5f

// Persistent scratch. Cross-launch invariants: g_cnt==0 and g_deg==0 at entry
// (guaranteed by static zero-init on first call, and by k_scan_dinv zeroing
// them after consumption on every call).
__device__ float  g_h[NN * DD];      // h = x @ W
__device__ float  g_deg[NN];         // weighted in-degree (excl. self loop)
__device__ float  g_dinv[NN];        // (deg+1)^{-1/2}
__device__ int    g_cnt[NN];         // integer in-degree (histogram)
__device__ int    g_off[NN];         // CSR begin offsets
__device__ int    g_cur[NN];         // fill cursor -> becomes CSR end
__device__ int2   g_csr[EE];         // {src, bits(normWeight)}
__device__ double g_stats[2];        // {sum, sumsq}

// ---------------------------------------------------------------------------
// K1: block-specialized: [0,G) gemm | [G,G+H) histogram | last block stats=0
// ---------------------------------------------------------------------------
__global__ void k_gemm_hist(const float* __restrict__ x,
                            const float* __restrict__ W,
                            const int* __restrict__ ei,
                            const float* __restrict__ ew,
                            int n, int E, int gemm_blks, int hist_blks) {
    __shared__ float Ws[DD * DD];
    __shared__ float xs[16 * DD];
    int bid = blockIdx.x;
    if (bid < gemm_blks) {
        for (int i = threadIdx.x; i < DD * DD; i += 256) Ws[i] = W[i];
        int base = bid * 16;
        for (int i = threadIdx.x; i < 16 * DD; i += 256) {
            int row = base + (i >> 6);
            xs[i] = (row < n) ? x[row * DD + (i & 63)] : 0.0f;
        }
        __syncthreads();
        int r0 = threadIdx.x >> 6;   // 0..3
        int d  = threadIdx.x & 63;
        float a0 = 0.f, a1 = 0.f, a2 = 0.f, a3 = 0.f;
#pragma unroll
        for (int k = 0; k < DD; k++) {
            float wv = Ws[k * DD + d];
            a0 += xs[(r0     ) * DD + k] * wv;
            a1 += xs[(r0 +  4) * DD + k] * wv;
            a2 += xs[(r0 +  8) * DD + k] * wv;
            a3 += xs[(r0 + 12) * DD + k] * wv;
        }
        int row = base + r0;
        if (row      < n) g_h[(row     ) * DD + d] = a0;
        if (row +  4 < n) g_h[(row +  4) * DD + d] = a1;
        if (row +  8 < n) g_h[(row +  8) * DD + d] = a2;
        if (row + 12 < n) g_h[(row + 12) * DD + d] = a3;
    } else if (bid < gemm_blks + hist_blks) {
        int e = (bid - gemm_blks) * 256 + threadIdx.x;
        if (e < E) {
            int c   = ei[E + e];
            float w = ew[e];
            atomicAdd(&g_deg[c], w);
            atomicAdd(&g_cnt[c], 1);
        }
    } else {
        if (threadIdx.x < 2) g_stats[threadIdx.x] = 0.0;
    }
}

// ---------------------------------------------------------------------------
// K2: block 0: exclusive scan of g_cnt -> g_off/g_cur, zero g_cnt
//     blocks >=1: dinv = rsqrt(deg + 1), zero g_deg
// ---------------------------------------------------------------------------
__global__ void k_scan_dinv(int n) {
    int tid = threadIdx.x;
    if (blockIdx.x == 0) {
        __shared__ int wsum[32];
        __shared__ int chunkbase;
        if (tid == 0) chunkbase = 0;
        __syncthreads();
        int lane = tid & 31, w = tid >> 5;
        int nchunks = (n + 1023) >> 10;
        for (int ch = 0; ch < nchunks; ch++) {
            int i = (ch << 10) + tid;
            int v = (i < n) ? g_cnt[i] : 0;
            int inc = v;
#pragma unroll
            for (int o = 1; o < 32; o <<= 1) {
                int t = __shfl_up_sync(0xffffffffu, inc, o);
                if (lane >= o) inc += t;
            }
            if (lane == 31) wsum[w] = inc;
            __syncthreads();
            if (w == 0) {
                int ws = wsum[lane];
#pragma unroll
                for (int o = 1; o < 32; o <<= 1) {
                    int t = __shfl_up_sync(0xffffffffu, ws, o);
                    if (lane >= o) ws += t;
                }
                wsum[lane] = ws;
            }
            __syncthreads();
            int wbase = (w == 0) ? 0 : wsum[w - 1];
            int excl  = chunkbase + wbase + inc - v;
            if (i < n) { g_off[i] = excl; g_cur[i] = excl; g_cnt[i] = 0; }
            int total = wsum[31];
            __syncthreads();
            if (tid == 0) chunkbase += total;
            __syncthreads();
        }
    } else {
        int i = (blockIdx.x - 1) * 1024 + tid;
        if (i < n) {
            g_dinv[i] = rsqrtf(g_deg[i] + 1.0f);
            g_deg[i]  = 0.0f;
        }
    }
}

// ---------------------------------------------------------------------------
// K3: CSR fill: for each edge store {src, dinv[src]*w*dinv[col]} at cursor
// ---------------------------------------------------------------------------
__global__ void k_fill(const int* __restrict__ ei, const float* __restrict__ ew,
                       int E) {
    int e = blockIdx.x * blockDim.x + threadIdx.x;
    if (e >= E) return;
    int r   = ei[e];
    int c   = ei[E + e];
    float wn = g_dinv[r] * ew[e] * g_dinv[c];
    int pos = atomicAdd(&g_cur[c], 1);
    g_csr[pos] = make_int2(r, __float_as_int(wn));
}

// ---------------------------------------------------------------------------
// K4: gather: out[node] = sum_in h[src]*wn + h[node]/deg + bias; stats accum
//     16 threads per node (one float4 each), 16 nodes per block
// ---------------------------------------------------------------------------
__global__ void k_gather(float* __restrict__ out, const float* __restrict__ b,
                         int n) {
    int tid  = threadIdx.x;
    int node = blockIdx.x * 16 + (tid >> 4);
    int seg  = tid & 15;
    float s = 0.f, sq = 0.f;
    if (node < n) {
        float4 acc = make_float4(0.f, 0.f, 0.f, 0.f);
        int p    = g_off[node];
        int pend = g_cur[node];       // begin + degree
        // unroll by 2 for MLP
        for (; p + 1 < pend; p += 2) {
            int2 e0 = g_csr[p];
            int2 e1 = g_csr[p + 1];
            float w0 = __int_as_float(e0.y);
            float w1 = __int_as_float(e1.y);
            const float4 h0 = *reinterpret_cast<const float4*>(
                g_h + (size_t)e0.x * DD + seg * 4);
            const float4 h1 = *reinterpret_cast<const float4*>(
                g_h + (size_t)e1.x * DD + seg * 4);
            acc.x += h0.x * w0 + h1.x * w1;
            acc.y += h0.y * w0 + h1.y * w1;
            acc.z += h0.z * w0 + h1.z * w1;
            acc.w += h0.w * w0 + h1.w * w1;
        }
        if (p < pend) {
            int2 e0 = g_csr[p];
            float w0 = __int_as_float(e0.y);
            const float4 h0 = *reinterpret_cast<const float4*>(
                g_h + (size_t)e0.x * DD + seg * 4);
            acc.x += h0.x * w0;
            acc.y += h0.y * w0;
            acc.z += h0.z * w0;
            acc.w += h0.w * w0;
        }
        float di = g_dinv[node];
        float sn = di * di;           // self-loop norm = 1/(deg+1)
        const float4 hs = *reinterpret_cast<const float4*>(
            g_h + (size_t)node * DD + seg * 4);
        const float4 bv = *reinterpret_cast<const float4*>(b + seg * 4);
        acc.x += hs.x * sn + bv.x;
        acc.y += hs.y * sn + bv.y;
        acc.z += hs.z * sn + bv.z;
        acc.w += hs.w * sn + bv.w;
        *reinterpret_cast<float4*>(out + (size_t)node * DD + seg * 4) = acc;
        s  = acc.x + acc.y + acc.z + acc.w;
        sq = acc.x * acc.x + acc.y * acc.y + acc.z * acc.z + acc.w * acc.w;
    }
    // block-wide double reduction -> 2 atomics
    double ds = (double)s, dq = (double)sq;
#pragma unroll
    for (int o = 16; o; o >>= 1) {
        ds += __shfl_down_sync(0xffffffffu, ds, o);
        dq += __shfl_down_sync(0xffffffffu, dq, o);
    }
    __shared__ double sh[16];
    int w = tid >> 5, l = tid & 31;
    if (l == 0) { sh[w] = ds; sh[8 + w] = dq; }
    __syncthreads();
    if (tid == 0) {
        double S = 0.0, Q = 0.0;
#pragma unroll
        for (int i = 0; i < 8; i++) { S += sh[i]; Q += sh[8 + i]; }
        atomicAdd(&g_stats[0], S);
        atomicAdd(&g_stats[1], Q);
    }
}

// ---------------------------------------------------------------------------
// K5: graph layernorm (global mean/std) + affine + relu
// ---------------------------------------------------------------------------
__global__ void k_norm(float* __restrict__ out,
                       const float* __restrict__ lnw,
                       const float* __restrict__ lnb, int nq, int total) {
    int t = blockIdx.x * blockDim.x + threadIdx.x;
    if (t >= nq) return;
    double S = g_stats[0], Q = g_stats[1];
    double m = S / (double)total;
    float mean = (float)m;
    float var  = (float)(Q / (double)total - m * m);
    var = var > 0.f ? var : 0.f;
    float istd = 1.0f / (sqrtf(var) + LN_EPS);
    int seg = t & 15;
    float4 v = reinterpret_cast<float4*>(out)[t];
    const float4 wv = *reinterpret_cast<const float4*>(lnw + seg * 4);
    const float4 bv = *reinterpret_cast<const float4*>(lnb + seg * 4);
    v.x = fmaxf((v.x - mean) * istd * wv.x + bv.x, 0.f);
    v.y = fmaxf((v.y - mean) * istd * wv.y + bv.y, 0.f);
    v.z = fmaxf((v.z - mean) * istd * wv.z + bv.z, 0.f);
    v.w = fmaxf((v.w - mean) * istd * wv.w + bv.w, 0.f);
    reinterpret_cast<float4*>(out)[t] = v;
}

// ---------------------------------------------------------------------------
extern "C" void kernel_launch(void* const* d_in, const int* in_sizes, int n_in,
                              void* d_out, int out_size) {
    const float* x   = (const float*)d_in[0];
    const float* ew  = (const float*)d_in[1];
    const float* W   = (const float*)d_in[2];
    const float* b   = (const float*)d_in[3];
    const float* lnw = (const float*)d_in[4];
    const float* lnb = (const float*)d_in[5];
    const int*   ei  = (const int*)d_in[6];

    int N = in_sizes[0] / DD;
    int E = in_sizes[1];
    float* out = (float*)d_out;

    int gemm_blks = (N + 15) / 16;
    int hist_blks = (E + 255) / 256;
    int nq = N * (DD / 4);

    k_gemm_hist<<<gemm_blks + hist_blks + 1, 256>>>(x, W, ei, ew, N, E,
                                                    gemm_blks, hist_blks);
    k_scan_dinv<<<1 + (N + 1023) / 1024, 1024>>>(N);
    k_fill     <<<(E + 255) / 256, 256>>>(ei, ew, E);
    k_gather   <<<(N + 15) / 16, 256>>>(out, b, N);
    k_norm     <<<(nq + 255) / 256, 256>>>(out, lnw, lnb, nq, N * DD);
}

// round 4
// speedup vs baseline: 1.3946x; 1.3946x over previous
#include <cuda_runtime.h>
#include <cuda_bf16.h>

#define NN 50000
#define EE 800000
#define DD 64
#define LN_EPS 1e-5f
#define SCAN_TILE 4096   // 1024 threads x 4 elems

// Persistent scratch. Cross-launch invariants restored every call:
//   g_cnt==0  (zeroed by scan kernel after consumption)
//   g_deg==0  (zeroed by dinv part after consumption)
//   g_tstat   (zeroed by util block in k_gemm_hist, consumed by scan)
__device__ float    g_h[NN * DD];    // h = x @ W
__device__ float    g_deg[NN];       // weighted in-degree (excl. self loop)
__device__ float    g_dinv[NN];      // (deg+1)^{-1/2}
__device__ int      g_cnt[NN];       // integer in-degree histogram
__device__ int      g_off[NN + 1];   // CSR offsets (+ sentinel = E)
__device__ int      g_eidx[EE];      // within-node slot of each edge
__device__ int2     g_csr[EE];       // {src, bits(normWeight)}
__device__ unsigned g_tstat[64];     // scan tile status: (val<<2)|flag
__device__ double   g_stats[2];      // {sum, sumsq}

__device__ __forceinline__ unsigned ldacq(const unsigned* p) {
    unsigned v;
    asm volatile("ld.acquire.gpu.global.b32 %0, [%1];"
                 : "=r"(v) : "l"(p) : "memory");
    return v;
}
__device__ __forceinline__ void strel(unsigned* p, unsigned v) {
    asm volatile("st.release.gpu.global.b32 [%0], %1;"
                 :: "l"(p), "r"(v) : "memory");
}

// ---------------------------------------------------------------------------
// K1: block-specialized: [0,G) gemm | [G,G+H) histogram(+eidx) | last: init
// ---------------------------------------------------------------------------
__global__ void k_gemm_hist(const float* __restrict__ x,
                            const float* __restrict__ W,
                            const int* __restrict__ ei,
                            const float* __restrict__ ew,
                            int n, int E, int gemm_blks, int hist_blks) {
    __shared__ float Ws[DD * DD];
    __shared__ float xs[16 * DD];
    int bid = blockIdx.x;
    if (bid < gemm_blks) {
        for (int i = threadIdx.x; i < DD * DD; i += 256) Ws[i] = W[i];
        int base = bid * 16;
        for (int i = threadIdx.x; i < 16 * DD; i += 256) {
            int row = base + (i >> 6);
            xs[i] = (row < n) ? x[row * DD + (i & 63)] : 0.0f;
        }
        __syncthreads();
        int r0 = threadIdx.x >> 6;   // 0..3
        int d  = threadIdx.x & 63;
        float a0 = 0.f, a1 = 0.f, a2 = 0.f, a3 = 0.f;
#pragma unroll
        for (int k = 0; k < DD; k++) {
            float wv = Ws[k * DD + d];
            a0 += xs[(r0     ) * DD + k] * wv;
            a1 += xs[(r0 +  4) * DD + k] * wv;
            a2 += xs[(r0 +  8) * DD + k] * wv;
            a3 += xs[(r0 + 12) * DD + k] * wv;
        }
        int row = base + r0;
        if (row      < n) g_h[(row     ) * DD + d] = a0;
        if (row +  4 < n) g_h[(row +  4) * DD + d] = a1;
        if (row +  8 < n) g_h[(row +  8) * DD + d] = a2;
        if (row + 12 < n) g_h[(row + 12) * DD + d] = a3;
    } else if (bid < gemm_blks + hist_blks) {
        int e = (bid - gemm_blks) * 256 + threadIdx.x;
        if (e < E) {
            int c   = ei[E + e];
            float w = ew[e];
            atomicAdd(&g_deg[c], w);
            g_eidx[e] = atomicAdd(&g_cnt[c], 1);
        }
    } else {
        if (threadIdx.x < 2)  g_stats[threadIdx.x] = 0.0;
        if (threadIdx.x < 64) g_tstat[threadIdx.x] = 0u;
    }
}

// ---------------------------------------------------------------------------
// K2: blocks [0,scan_tiles): decoupled-lookback exclusive scan of g_cnt
//     blocks [scan_tiles,..): dinv = rsqrt(deg+1), zero g_deg
//     All scan tiles are resident concurrently (13 + 49 blocks << 148 SMs),
//     so spinning cannot deadlock.
// ---------------------------------------------------------------------------
__global__ void k_scan_dinv(int n, int scan_tiles) {
    int tid = threadIdx.x;
    if (blockIdx.x < scan_tiles) {
        int tile = blockIdx.x;
        int i0 = tile * SCAN_TILE + tid * 4;
        int v0 = (i0     < n) ? g_cnt[i0]     : 0;
        int v1 = (i0 + 1 < n) ? g_cnt[i0 + 1] : 0;
        int v2 = (i0 + 2 < n) ? g_cnt[i0 + 2] : 0;
        int v3 = (i0 + 3 < n) ? g_cnt[i0 + 3] : 0;
        int T = v0 + v1 + v2 + v3;

        int lane = tid & 31, w = tid >> 5;
        int inc = T;
#pragma unroll
        for (int o = 1; o < 32; o <<= 1) {
            int t = __shfl_up_sync(0xffffffffu, inc, o);
            if (lane >= o) inc += t;
        }
        __shared__ int wsum[32];
        __shared__ int s_prefix;
        if (lane == 31) wsum[w] = inc;
        __syncthreads();
        if (w == 0) {
            int ws = wsum[lane];
#pragma unroll
            for (int o = 1; o < 32; o <<= 1) {
                int t = __shfl_up_sync(0xffffffffu, ws, o);
                if (lane >= o) ws += t;
            }
            wsum[lane] = ws;
        }
        __syncthreads();
        int excl = inc - T + ((w > 0) ? wsum[w - 1] : 0);
        int agg  = wsum[31];

        if (tid == 0) {
            int prefix = 0;
            if (tile == 0) {
                strel(&g_tstat[0], ((unsigned)agg << 2) | 2u);
            } else {
                strel(&g_tstat[tile], ((unsigned)agg << 2) | 1u);
                for (int j = tile - 1; j >= 0; j--) {
                    unsigned s;
                    do { s = ldacq(&g_tstat[j]); } while ((s & 3u) == 0u);
                    prefix += (int)(s >> 2);
                    if ((s & 3u) == 2u) break;
                }
                strel(&g_tstat[tile], ((unsigned)(prefix + agg) << 2) | 2u);
            }
            s_prefix = prefix;
            if (tile == scan_tiles - 1) g_off[n] = prefix + agg;  // == E
        }
        __syncthreads();
        int pref = s_prefix + excl;
        if (i0     < n) { g_off[i0]     = pref;              g_cnt[i0]     = 0; }
        if (i0 + 1 < n) { g_off[i0 + 1] = pref + v0;         g_cnt[i0 + 1] = 0; }
        if (i0 + 2 < n) { g_off[i0 + 2] = pref + v0 + v1;    g_cnt[i0 + 2] = 0; }
        if (i0 + 3 < n) { g_off[i0 + 3] = pref + v0 + v1 + v2; g_cnt[i0 + 3] = 0; }
    } else {
        int i = (blockIdx.x - scan_tiles) * 1024 + tid;
        if (i < n) {
            g_dinv[i] = rsqrtf(g_deg[i] + 1.0f);
            g_deg[i]  = 0.0f;
        }
    }
}

// ---------------------------------------------------------------------------
// K3: CSR fill (atomic-free): pos = off[col] + eidx[e]
// ---------------------------------------------------------------------------
__global__ void k_fill(const int* __restrict__ ei, const float* __restrict__ ew,
                       int E) {
    int e = blockIdx.x * blockDim.x + threadIdx.x;
    if (e >= E) return;
    int r = ei[e];
    int c = ei[E + e];
    float wn = g_dinv[r] * ew[e] * g_dinv[c];
    int pos = g_off[c] + g_eidx[e];
    g_csr[pos] = make_int2(r, __float_as_int(wn));
}

// ---------------------------------------------------------------------------
// K4: gather: out[node] = sum_in h[src]*wn + h[node]/(deg+1) + bias; + stats
//     16 threads per node (one float4 each), 16 nodes per block, unroll 4
// ---------------------------------------------------------------------------
__global__ void k_gather(float* __restrict__ out, const float* __restrict__ b,
                         int n) {
    int tid  = threadIdx.x;
    int node = blockIdx.x * 16 + (tid >> 4);
    int seg  = tid & 15;
    float s = 0.f, sq = 0.f;
    if (node < n) {
        float4 acc = make_float4(0.f, 0.f, 0.f, 0.f);
        int p    = g_off[node];
        int pend = g_off[node + 1];
        for (; p + 3 < pend; p += 4) {
            int2 e0 = g_csr[p];
            int2 e1 = g_csr[p + 1];
            int2 e2 = g_csr[p + 2];
            int2 e3 = g_csr[p + 3];
            const float4 h0 = *reinterpret_cast<const float4*>(g_h + (size_t)e0.x * DD + seg * 4);
            const float4 h1 = *reinterpret_cast<const float4*>(g_h + (size_t)e1.x * DD + seg * 4);
            const float4 h2 = *reinterpret_cast<const float4*>(g_h + (size_t)e2.x * DD + seg * 4);
            const float4 h3 = *reinterpret_cast<const float4*>(g_h + (size_t)e3.x * DD + seg * 4);
            float w0 = __int_as_float(e0.y), w1 = __int_as_float(e1.y);
            float w2 = __int_as_float(e2.y), w3 = __int_as_float(e3.y);
            acc.x += h0.x * w0 + h1.x * w1 + h2.x * w2 + h3.x * w3;
            acc.y += h0.y * w0 + h1.y * w1 + h2.y * w2 + h3.y * w3;
            acc.z += h0.z * w0 + h1.z * w1 + h2.z * w2 + h3.z * w3;
            acc.w += h0.w * w0 + h1.w * w1 + h2.w * w2 + h3.w * w3;
        }
        for (; p < pend; p++) {
            int2 e0 = g_csr[p];
            float w0 = __int_as_float(e0.y);
            const float4 h0 = *reinterpret_cast<const float4*>(g_h + (size_t)e0.x * DD + seg * 4);
            acc.x += h0.x * w0;
            acc.y += h0.y * w0;
            acc.z += h0.z * w0;
            acc.w += h0.w * w0;
        }
        float di = g_dinv[node];
        float sn = di * di;           // self-loop norm = 1/(deg+1)
        const float4 hs = *reinterpret_cast<const float4*>(g_h + (size_t)node * DD + seg * 4);
        const float4 bv = *reinterpret_cast<const float4*>(b + seg * 4);
        acc.x += hs.x * sn + bv.x;
        acc.y += hs.y * sn + bv.y;
        acc.z += hs.z * sn + bv.z;
        acc.w += hs.w * sn + bv.w;
        *reinterpret_cast<float4*>(out + (size_t)node * DD + seg * 4) = acc;
        s  = acc.x + acc.y + acc.z + acc.w;
        sq = acc.x * acc.x + acc.y * acc.y + acc.z * acc.z + acc.w * acc.w;
    }
    double ds = (double)s, dq = (double)sq;
#pragma unroll
    for (int o = 16; o; o >>= 1) {
        ds += __shfl_down_sync(0xffffffffu, ds, o);
        dq += __shfl_down_sync(0xffffffffu, dq, o);
    }
    __shared__ double sh[16];
    int w = tid >> 5, l = tid & 31;
    if (l == 0) { sh[w] = ds; sh[8 + w] = dq; }
    __syncthreads();
    if (tid == 0) {
        double S = 0.0, Q = 0.0;
#pragma unroll
        for (int i = 0; i < 8; i++) { S += sh[i]; Q += sh[8 + i]; }
        atomicAdd(&g_stats[0], S);
        atomicAdd(&g_stats[1], Q);
    }
}

// ---------------------------------------------------------------------------
// K5: graph layernorm (global mean/std) + affine + relu
// ---------------------------------------------------------------------------
__global__ void k_norm(float* __restrict__ out,
                       const float* __restrict__ lnw,
                       const float* __restrict__ lnb, int nq, int total) {
    int t = blockIdx.x * blockDim.x + threadIdx.x;
    if (t >= nq) return;
    double S = g_stats[0], Q = g_stats[1];
    double m = S / (double)total;
    float mean = (float)m;
    float var  = (float)(Q / (double)total - m * m);
    var = var > 0.f ? var : 0.f;
    float istd = 1.0f / (sqrtf(var) + LN_EPS);
    int seg = t & 15;
    float4 v = reinterpret_cast<float4*>(out)[t];
    const float4 wv = *reinterpret_cast<const float4*>(lnw + seg * 4);
    const float4 bv = *reinterpret_cast<const float4*>(lnb + seg * 4);
    v.x = fmaxf((v.x - mean) * istd * wv.x + bv.x, 0.f);
    v.y = fmaxf((v.y - mean) * istd * wv.y + bv.y, 0.f);
    v.z = fmaxf((v.z - mean) * istd * wv.z + bv.z, 0.f);
    v.w = fmaxf((v.w - mean) * istd * wv.w + bv.w, 0.f);
    reinterpret_cast<float4*>(out)[t] = v;
}

// ---------------------------------------------------------------------------
extern "C" void kernel_launch(void* const* d_in, const int* in_sizes, int n_in,
                              void* d_out, int out_size) {
    const float* x   = (const float*)d_in[0];
    const float* ew  = (const float*)d_in[1];
    const float* W   = (const float*)d_in[2];
    const float* b   = (const float*)d_in[3];
    const float* lnw = (const float*)d_in[4];
    const float* lnb = (const float*)d_in[5];
    const int*   ei  = (const int*)d_in[6];

    int N = in_sizes[0] / DD;
    int E = in_sizes[1];
    float* out = (float*)d_out;

    int gemm_blks  = (N + 15) / 16;
    int hist_blks  = (E + 255) / 256;
    int scan_tiles = (N + SCAN_TILE - 1) / SCAN_TILE;   // 13
    int dinv_blks  = (N + 1023) / 1024;                 // 49
    int nq = N * (DD / 4);

    k_gemm_hist<<<gemm_blks + hist_blks + 1, 256>>>(x, W, ei, ew, N, E,
                                                    gemm_blks, hist_blks);
    k_scan_dinv<<<scan_tiles + dinv_blks, 1024>>>(N, scan_tiles);
    k_fill     <<<(E + 255) / 256, 256>>>(ei, ew, E);
    k_gather   <<<(N + 15) / 16, 256>>>(out, b, N);
    k_norm     <<<(nq + 255) / 256, 256>>>(out, lnw, lnb, nq, N * DD);
}

// round 5
// speedup vs baseline: 1.4284x; 1.0242x over previous
#include <cuda_runtime.h>
#include <cuda_fp16.h>

#define NN 50000
#define EE 800000
#define DD 64
#define LN_EPS 1e-5f
#define SCAN_TILE 4096   // 1024 threads x 4 elems

// Persistent scratch. Cross-launch invariants restored every call:
//   g_cnt==0  (zeroed by scan kernel after consumption)
//   g_deg==0  (zeroed by dinv part after consumption)
//   g_tstat   (zeroed by util block in k_gemm_hist, consumed by scan)
__device__ float    g_h[NN * DD];    // h = x @ W  (fp32, self-loop term)
__device__ __half   g_hh[NN * DD];   // h in fp16  (neighbor gather)
__device__ float    g_deg[NN];       // weighted in-degree (excl. self loop)
__device__ float    g_dinv[NN];      // (deg+1)^{-1/2}
__device__ int      g_cnt[NN];       // integer in-degree histogram
__device__ int      g_off[NN + 1];   // CSR offsets (+ sentinel = E)
__device__ int      g_eidx[EE];      // within-node slot of each edge
__device__ int2     g_csr[EE];       // {src, bits(normWeight)}
__device__ unsigned g_tstat[64];     // scan tile status: (val<<2)|flag
__device__ double   g_stats[2];      // {sum, sumsq}

__device__ __forceinline__ unsigned ldacq(const unsigned* p) {
    unsigned v;
    asm volatile("ld.acquire.gpu.global.b32 %0, [%1];"
                 : "=r"(v) : "l"(p) : "memory");
    return v;
}
__device__ __forceinline__ void strel(unsigned* p, unsigned v) {
    asm volatile("st.release.gpu.global.b32 [%0], %1;"
                 :: "l"(p), "r"(v) : "memory");
}

// fma 8 halfs (packed in uint4) * w into 8 fp32 accumulators
__device__ __forceinline__ void fma8(float* acc, uint4 r, float w) {
    const __half2* h = reinterpret_cast<const __half2*>(&r);
#pragma unroll
    for (int i = 0; i < 4; i++) {
        float2 f = __half22float2(h[i]);
        acc[2 * i]     += f.x * w;
        acc[2 * i + 1] += f.y * w;
    }
}

// ---------------------------------------------------------------------------
// K1: block-specialized: [0,G) gemm | [G,G+H) histogram(+eidx) | last: init
// ---------------------------------------------------------------------------
__global__ void k_gemm_hist(const float* __restrict__ x,
                            const float* __restrict__ W,
                            const int* __restrict__ ei,
                            const float* __restrict__ ew,
                            int n, int E, int gemm_blks, int hist_blks) {
    __shared__ float Ws[DD * DD];
    __shared__ float xs[16 * DD];
    int bid = blockIdx.x;
    if (bid < gemm_blks) {
        for (int i = threadIdx.x; i < DD * DD; i += 256) Ws[i] = W[i];
        int base = bid * 16;
        for (int i = threadIdx.x; i < 16 * DD; i += 256) {
            int row = base + (i >> 6);
            xs[i] = (row < n) ? x[row * DD + (i & 63)] : 0.0f;
        }
        __syncthreads();
        int r0 = threadIdx.x >> 6;   // 0..3
        int d  = threadIdx.x & 63;
        float a0 = 0.f, a1 = 0.f, a2 = 0.f, a3 = 0.f;
#pragma unroll
        for (int k = 0; k < DD; k++) {
            float wv = Ws[k * DD + d];
            a0 += xs[(r0     ) * DD + k] * wv;
            a1 += xs[(r0 +  4) * DD + k] * wv;
            a2 += xs[(r0 +  8) * DD + k] * wv;
            a3 += xs[(r0 + 12) * DD + k] * wv;
        }
        int row = base + r0;
        if (row < n) {
            g_h [(row) * DD + d] = a0;
            g_hh[(row) * DD + d] = __float2half(a0);
        }
        if (row + 4 < n) {
            g_h [(row + 4) * DD + d] = a1;
            g_hh[(row + 4) * DD + d] = __float2half(a1);
        }
        if (row + 8 < n) {
            g_h [(row + 8) * DD + d] = a2;
            g_hh[(row + 8) * DD + d] = __float2half(a2);
        }
        if (row + 12 < n) {
            g_h [(row + 12) * DD + d] = a3;
            g_hh[(row + 12) * DD + d] = __float2half(a3);
        }
    } else if (bid < gemm_blks + hist_blks) {
        int e = (bid - gemm_blks) * 256 + threadIdx.x;
        if (e < E) {
            int c   = ei[E + e];
            float w = ew[e];
            atomicAdd(&g_deg[c], w);
            g_eidx[e] = atomicAdd(&g_cnt[c], 1);
        }
    } else {
        if (threadIdx.x < 2)  g_stats[threadIdx.x] = 0.0;
        if (threadIdx.x < 64) g_tstat[threadIdx.x] = 0u;
    }
}

// ---------------------------------------------------------------------------
// K2: blocks [0,scan_tiles): decoupled-lookback exclusive scan of g_cnt
//     blocks [scan_tiles,..): dinv = rsqrt(deg+1), zero g_deg
// ---------------------------------------------------------------------------
__global__ void k_scan_dinv(int n, int scan_tiles) {
    int tid = threadIdx.x;
    if (blockIdx.x < scan_tiles) {
        int tile = blockIdx.x;
        int i0 = tile * SCAN_TILE + tid * 4;
        int v0 = (i0     < n) ? g_cnt[i0]     : 0;
        int v1 = (i0 + 1 < n) ? g_cnt[i0 + 1] : 0;
        int v2 = (i0 + 2 < n) ? g_cnt[i0 + 2] : 0;
        int v3 = (i0 + 3 < n) ? g_cnt[i0 + 3] : 0;
        int T = v0 + v1 + v2 + v3;

        int lane = tid & 31, w = tid >> 5;
        int inc = T;
#pragma unroll
        for (int o = 1; o < 32; o <<= 1) {
            int t = __shfl_up_sync(0xffffffffu, inc, o);
            if (lane >= o) inc += t;
        }
        __shared__ int wsum[32];
        __shared__ int s_prefix;
        if (lane == 31) wsum[w] = inc;
        __syncthreads();
        if (w == 0) {
            int ws = wsum[lane];
#pragma unroll
            for (int o = 1; o < 32; o <<= 1) {
                int t = __shfl_up_sync(0xffffffffu, ws, o);
                if (lane >= o) ws += t;
            }
            wsum[lane] = ws;
        }
        __syncthreads();
        int excl = inc - T + ((w > 0) ? wsum[w - 1] : 0);
        int agg  = wsum[31];

        if (tid == 0) {
            int prefix = 0;
            if (tile == 0) {
                strel(&g_tstat[0], ((unsigned)agg << 2) | 2u);
            } else {
                strel(&g_tstat[tile], ((unsigned)agg << 2) | 1u);
                for (int j = tile - 1; j >= 0; j--) {
                    unsigned s;
                    do { s = ldacq(&g_tstat[j]); } while ((s & 3u) == 0u);
                    prefix += (int)(s >> 2);
                    if ((s & 3u) == 2u) break;
                }
                strel(&g_tstat[tile], ((unsigned)(prefix + agg) << 2) | 2u);
            }
            s_prefix = prefix;
            if (tile == scan_tiles - 1) g_off[n] = prefix + agg;  // == E
        }
        __syncthreads();
        int pref = s_prefix + excl;
        if (i0     < n) { g_off[i0]     = pref;                g_cnt[i0]     = 0; }
        if (i0 + 1 < n) { g_off[i0 + 1] = pref + v0;           g_cnt[i0 + 1] = 0; }
        if (i0 + 2 < n) { g_off[i0 + 2] = pref + v0 + v1;      g_cnt[i0 + 2] = 0; }
        if (i0 + 3 < n) { g_off[i0 + 3] = pref + v0 + v1 + v2; g_cnt[i0 + 3] = 0; }
    } else {
        int i = (blockIdx.x - scan_tiles) * 1024 + tid;
        if (i < n) {
            g_dinv[i] = rsqrtf(g_deg[i] + 1.0f);
            g_deg[i]  = 0.0f;
        }
    }
}

// ---------------------------------------------------------------------------
// K3: CSR fill (atomic-free): pos = off[col] + eidx[e]
// ---------------------------------------------------------------------------
__global__ void k_fill(const int* __restrict__ ei, const float* __restrict__ ew,
                       int E) {
    int e = blockIdx.x * blockDim.x + threadIdx.x;
    if (e >= E) return;
    int r = ei[e];
    int c = ei[E + e];
    float wn = g_dinv[r] * ew[e] * g_dinv[c];
    int pos = g_off[c] + g_eidx[e];
    g_csr[pos] = make_int2(r, __float_as_int(wn));
}

// ---------------------------------------------------------------------------
// K4: gather (fp16 rows): out[node] = sum_in h16[src]*wn + h32[node]/(deg+1)
//     + bias; fused stats. 8 threads per node (8 features each = one uint4 of
//     halfs), 32 nodes per block.
// ---------------------------------------------------------------------------
__global__ void k_gather(float* __restrict__ out, const float* __restrict__ b,
                         int n) {
    int tid  = threadIdx.x;
    int node = blockIdx.x * 32 + (tid >> 3);
    int sub  = tid & 7;          // feature octet: features [sub*8, sub*8+8)
    float s = 0.f, sq = 0.f;
    if (node < n) {
        float acc[8] = {0.f, 0.f, 0.f, 0.f, 0.f, 0.f, 0.f, 0.f};
        const uint4* hrow = reinterpret_cast<const uint4*>(g_hh) ;
        int p    = g_off[node];
        int pend = g_off[node + 1];
        for (; p + 1 < pend; p += 2) {
            int2 e0 = g_csr[p];
            int2 e1 = g_csr[p + 1];
            uint4 r0 = hrow[(size_t)e0.x * 8 + sub];
            uint4 r1 = hrow[(size_t)e1.x * 8 + sub];
            fma8(acc, r0, __int_as_float(e0.y));
            fma8(acc, r1, __int_as_float(e1.y));
        }
        if (p < pend) {
            int2 e0 = g_csr[p];
            uint4 r0 = hrow[(size_t)e0.x * 8 + sub];
            fma8(acc, r0, __int_as_float(e0.y));
        }
        float di = g_dinv[node];
        float sn = di * di;      // self-loop norm = 1/(deg+1)
        const float4 hs0 = *reinterpret_cast<const float4*>(
            g_h + (size_t)node * DD + sub * 8);
        const float4 hs1 = *reinterpret_cast<const float4*>(
            g_h + (size_t)node * DD + sub * 8 + 4);
        const float4 bv0 = *reinterpret_cast<const float4*>(b + sub * 8);
        const float4 bv1 = *reinterpret_cast<const float4*>(b + sub * 8 + 4);
        acc[0] += hs0.x * sn + bv0.x;
        acc[1] += hs0.y * sn + bv0.y;
        acc[2] += hs0.z * sn + bv0.z;
        acc[3] += hs0.w * sn + bv0.w;
        acc[4] += hs1.x * sn + bv1.x;
        acc[5] += hs1.y * sn + bv1.y;
        acc[6] += hs1.z * sn + bv1.z;
        acc[7] += hs1.w * sn + bv1.w;
        float4* orow = reinterpret_cast<float4*>(out + (size_t)node * DD + sub * 8);
        orow[0] = make_float4(acc[0], acc[1], acc[2], acc[3]);
        orow[1] = make_float4(acc[4], acc[5], acc[6], acc[7]);
#pragma unroll
        for (int i = 0; i < 8; i++) { s += acc[i]; sq += acc[i] * acc[i]; }
    }
    double ds = (double)s, dq = (double)sq;
#pragma unroll
    for (int o = 16; o; o >>= 1) {
        ds += __shfl_down_sync(0xffffffffu, ds, o);
        dq += __shfl_down_sync(0xffffffffu, dq, o);
    }
    __shared__ double sh[16];
    int w = tid >> 5, l = tid & 31;
    if (l == 0) { sh[w] = ds; sh[8 + w] = dq; }
    __syncthreads();
    if (tid == 0) {
        double S = 0.0, Q = 0.0;
#pragma unroll
        for (int i = 0; i < 8; i++) { S += sh[i]; Q += sh[8 + i]; }
        atomicAdd(&g_stats[0], S);
        atomicAdd(&g_stats[1], Q);
    }
}

// ---------------------------------------------------------------------------
// K5: graph layernorm (global mean/std) + affine + relu
// ---------------------------------------------------------------------------
__global__ void k_norm(float* __restrict__ out,
                       const float* __restrict__ lnw,
                       const float* __restrict__ lnb, int nq, int total) {
    int t = blockIdx.x * blockDim.x + threadIdx.x;
    if (t >= nq) return;
    double S = g_stats[0], Q = g_stats[1];
    double m = S / (double)total;
    float mean = (float)m;
    float var  = (float)(Q / (double)total - m * m);
    var = var > 0.f ? var : 0.f;
    float istd = 1.0f / (sqrtf(var) + LN_EPS);
    int seg = t & 15;
    float4 v = reinterpret_cast<float4*>(out)[t];
    const float4 wv = *reinterpret_cast<const float4*>(lnw + seg * 4);
    const float4 bv = *reinterpret_cast<const float4*>(lnb + seg * 4);
    v.x = fmaxf((v.x - mean) * istd * wv.x + bv.x, 0.f);
    v.y = fmaxf((v.y - mean) * istd * wv.y + bv.y, 0.f);
    v.z = fmaxf((v.z - mean) * istd * wv.z + bv.z, 0.f);
    v.w = fmaxf((v.w - mean) * istd * wv.w + bv.w, 0.f);
    reinterpret_cast<float4*>(out)[t] = v;
}

// ---------------------------------------------------------------------------
extern "C" void kernel_launch(void* const* d_in, const int* in_sizes, int n_in,
                              void* d_out, int out_size) {
    const float* x   = (const float*)d_in[0];
    const float* ew  = (const float*)d_in[1];
    const float* W   = (const float*)d_in[2];
    const float* b   = (const float*)d_in[3];
    const float* lnw = (const float*)d_in[4];
    const float* lnb = (const float*)d_in[5];
    const int*   ei  = (const int*)d_in[6];

    int N = in_sizes[0] / DD;
    int E = in_sizes[1];
    float* out = (float*)d_out;

    int gemm_blks  = (N + 15) / 16;
    int hist_blks  = (E + 255) / 256;
    int scan_tiles = (N + SCAN_TILE - 1) / SCAN_TILE;   // 13
    int dinv_blks  = (N + 1023) / 1024;                 // 49
    int nq = N * (DD / 4);

    k_gemm_hist<<<gemm_blks + hist_blks + 1, 256>>>(x, W, ei, ew, N, E,
                                                    gemm_blks, hist_blks);
    k_scan_dinv<<<scan_tiles + dinv_blks, 1024>>>(N, scan_tiles);
    k_fill     <<<(E + 255) / 256, 256>>>(ei, ew, E);
    k_gather   <<<(N + 31) / 32, 256>>>(out, b, N);
    k_norm     <<<(nq + 255) / 256, 256>>>(out, lnw, lnb, nq, N * DD);
}

// round 6
// speedup vs baseline: 1.4560x; 1.0193x over previous
#include <cuda_runtime.h>
#include <cuda_fp16.h>

#define NN 50000
#define EE 800000
#define DD 64
#define LN_EPS 1e-5f
#define SCAN_TILE 4096   // 1024 threads x 4 elems

// Persistent scratch. Cross-launch invariants restored every call:
//   g_cnt==0  (zeroed by scan kernel after consumption)
//   g_deg==0  (zeroed by dinv part after consumption)
//   g_tstat   (zeroed by util block in k_gemm_hist, consumed by scan)
__device__ float    g_h[NN * DD];    // h = x @ W  (fp32, self-loop term)
__device__ __half   g_hh[NN * DD];   // h in fp16  (neighbor gather)
__device__ float    g_deg[NN];       // weighted in-degree (excl. self loop)
__device__ float    g_dinv[NN];      // (deg+1)^{-1/2}
__device__ int      g_cnt[NN];       // integer in-degree histogram
__device__ int      g_off[NN + 1];   // CSR offsets (+ sentinel = E)
__device__ int      g_eidx[EE];      // within-node slot of each edge
__device__ int2     g_csr[EE];       // {src, bits(normWeight)}
__device__ unsigned g_tstat[64];     // scan tile status: (val<<2)|flag
__device__ double   g_stats[2];      // {sum, sumsq}

__device__ __forceinline__ unsigned ldacq(const unsigned* p) {
    unsigned v;
    asm volatile("ld.acquire.gpu.global.b32 %0, [%1];"
                 : "=r"(v) : "l"(p) : "memory");
    return v;
}
__device__ __forceinline__ void strel(unsigned* p, unsigned v) {
    asm volatile("st.release.gpu.global.b32 [%0], %1;"
                 :: "l"(p), "r"(v) : "memory");
}

// fma 8 halfs (packed in uint4) * w into 8 fp32 accumulators
__device__ __forceinline__ void fma8(float* acc, uint4 r, float w) {
    const __half2* h = reinterpret_cast<const __half2*>(&r);
#pragma unroll
    for (int i = 0; i < 4; i++) {
        float2 f = __half22float2(h[i]);
        acc[2 * i]     += f.x * w;
        acc[2 * i + 1] += f.y * w;
    }
}

// ---------------------------------------------------------------------------
// K1: block-specialized: [0,G) gemm(32 rows/blk) | [G,G+H) hist | last: init
// ---------------------------------------------------------------------------
__global__ void k_gemm_hist(const float* __restrict__ x,
                            const float* __restrict__ W,
                            const int* __restrict__ ei,
                            const float* __restrict__ ew,
                            int n, int E, int gemm_blks, int hist_blks) {
    __shared__ float Ws[DD * DD];     // 16 KB
    __shared__ float xs[32 * DD];     // 8 KB
    int bid = blockIdx.x;
    if (bid < gemm_blks) {
        for (int i = threadIdx.x; i < DD * DD; i += 256) Ws[i] = W[i];
        int base = bid * 32;
        for (int i = threadIdx.x; i < 32 * DD; i += 256) {
            int row = base + (i >> 6);
            xs[i] = (row < n) ? x[row * DD + (i & 63)] : 0.0f;
        }
        __syncthreads();
        int r0 = threadIdx.x >> 6;   // 0..3
        int d  = threadIdx.x & 63;
        float a[8] = {0.f, 0.f, 0.f, 0.f, 0.f, 0.f, 0.f, 0.f};
#pragma unroll
        for (int k4 = 0; k4 < 16; k4++) {
            float4 xv[8];
#pragma unroll
            for (int i = 0; i < 8; i++)
                xv[i] = *reinterpret_cast<const float4*>(
                    &xs[(r0 + i * 4) * DD + k4 * 4]);
#pragma unroll
            for (int kk = 0; kk < 4; kk++) {
                float wv = Ws[(k4 * 4 + kk) * DD + d];
#pragma unroll
                for (int i = 0; i < 8; i++)
                    a[i] += reinterpret_cast<const float*>(&xv[i])[kk] * wv;
            }
        }
#pragma unroll
        for (int i = 0; i < 8; i++) {
            int row = base + r0 + i * 4;
            if (row < n) {
                g_h [(size_t)row * DD + d] = a[i];
                g_hh[(size_t)row * DD + d] = __float2half(a[i]);
            }
        }
    } else if (bid < gemm_blks + hist_blks) {
        int e = (bid - gemm_blks) * 256 + threadIdx.x;
        if (e < E) {
            int c   = ei[E + e];
            float w = ew[e];
            asm volatile("red.global.add.f32 [%0], %1;"
                         :: "l"(&g_deg[c]), "f"(w) : "memory");
            g_eidx[e] = atomicAdd(&g_cnt[c], 1);
        }
    } else {
        if (threadIdx.x < 2)  g_stats[threadIdx.x] = 0.0;
        if (threadIdx.x < 64) g_tstat[threadIdx.x] = 0u;
    }
}

// ---------------------------------------------------------------------------
// K2: blocks [0,scan_tiles): decoupled-lookback exclusive scan of g_cnt
//     blocks [scan_tiles,..): dinv = rsqrt(deg+1), zero g_deg
// ---------------------------------------------------------------------------
__global__ void k_scan_dinv(int n, int scan_tiles) {
    int tid = threadIdx.x;
    if (blockIdx.x < scan_tiles) {
        int tile = blockIdx.x;
        int i0 = tile * SCAN_TILE + tid * 4;
        int v0 = (i0     < n) ? g_cnt[i0]     : 0;
        int v1 = (i0 + 1 < n) ? g_cnt[i0 + 1] : 0;
        int v2 = (i0 + 2 < n) ? g_cnt[i0 + 2] : 0;
        int v3 = (i0 + 3 < n) ? g_cnt[i0 + 3] : 0;
        int T = v0 + v1 + v2 + v3;

        int lane = tid & 31, w = tid >> 5;
        int inc = T;
#pragma unroll
        for (int o = 1; o < 32; o <<= 1) {
            int t = __shfl_up_sync(0xffffffffu, inc, o);
            if (lane >= o) inc += t;
        }
        __shared__ int wsum[32];
        __shared__ int s_prefix;
        if (lane == 31) wsum[w] = inc;
        __syncthreads();
        if (w == 0) {
            int ws = wsum[lane];
#pragma unroll
            for (int o = 1; o < 32; o <<= 1) {
                int t = __shfl_up_sync(0xffffffffu, ws, o);
                if (lane >= o) ws += t;
            }
            wsum[lane] = ws;
        }
        __syncthreads();
        int excl = inc - T + ((w > 0) ? wsum[w - 1] : 0);
        int agg  = wsum[31];

        if (tid == 0) {
            int prefix = 0;
            if (tile == 0) {
                strel(&g_tstat[0], ((unsigned)agg << 2) | 2u);
            } else {
                strel(&g_tstat[tile], ((unsigned)agg << 2) | 1u);
                for (int j = tile - 1; j >= 0; j--) {
                    unsigned s;
                    do { s = ldacq(&g_tstat[j]); } while ((s & 3u) == 0u);
                    prefix += (int)(s >> 2);
                    if ((s & 3u) == 2u) break;
                }
                strel(&g_tstat[tile], ((unsigned)(prefix + agg) << 2) | 2u);
            }
            s_prefix = prefix;
            if (tile == scan_tiles - 1) g_off[n] = prefix + agg;  // == E
        }
        __syncthreads();
        int pref = s_prefix + excl;
        if (i0     < n) { g_off[i0]     = pref;                g_cnt[i0]     = 0; }
        if (i0 + 1 < n) { g_off[i0 + 1] = pref + v0;           g_cnt[i0 + 1] = 0; }
        if (i0 + 2 < n) { g_off[i0 + 2] = pref + v0 + v1;      g_cnt[i0 + 2] = 0; }
        if (i0 + 3 < n) { g_off[i0 + 3] = pref + v0 + v1 + v2; g_cnt[i0 + 3] = 0; }
    } else {
        int i = (blockIdx.x - scan_tiles) * 1024 + tid;
        if (i < n) {
            g_dinv[i] = rsqrtf(g_deg[i] + 1.0f);
            g_deg[i]  = 0.0f;
        }
    }
}

// ---------------------------------------------------------------------------
// K3: CSR fill (atomic-free): pos = off[col] + eidx[e]; 2 edges per thread
// ---------------------------------------------------------------------------
__global__ void k_fill(const int* __restrict__ ei, const float* __restrict__ ew,
                       int E, int vec) {
    int t = blockIdx.x * blockDim.x + threadIdx.x;
    if (vec) {
        int e = t * 2;
        if (e + 1 < E) {
            int2   r  = *reinterpret_cast<const int2*>(ei + e);
            int2   c  = *reinterpret_cast<const int2*>(ei + E + e);
            float2 w  = *reinterpret_cast<const float2*>(ew + e);
            int2   ix = *reinterpret_cast<const int2*>(g_eidx + e);
            float wn0 = g_dinv[r.x] * w.x * g_dinv[c.x];
            float wn1 = g_dinv[r.y] * w.y * g_dinv[c.y];
            g_csr[g_off[c.x] + ix.x] = make_int2(r.x, __float_as_int(wn0));
            g_csr[g_off[c.y] + ix.y] = make_int2(r.y, __float_as_int(wn1));
        } else if (e < E) {
            int r = ei[e], c = ei[E + e];
            float wn = g_dinv[r] * ew[e] * g_dinv[c];
            g_csr[g_off[c] + g_eidx[e]] = make_int2(r, __float_as_int(wn));
        }
    } else {
        if (t < E) {
            int r = ei[t], c = ei[E + t];
            float wn = g_dinv[r] * ew[t] * g_dinv[c];
            g_csr[g_off[c] + g_eidx[t]] = make_int2(r, __float_as_int(wn));
        }
    }
}

// ---------------------------------------------------------------------------
// K4: warp-cooperative gather: 8 threads/node, 8-edge batches.
//     Threads of a group batch-load 8 CSR entries (coalesced), broadcast via
//     sub-group shuffles (mask = group byte; control flow uniform per group),
//     each thread fmas its feature octet -> 8 row loads in flight.
// ---------------------------------------------------------------------------
__global__ void k_gather(float* __restrict__ out, const float* __restrict__ b,
                         int n) {
    int tid   = threadIdx.x;
    int node  = blockIdx.x * 32 + (tid >> 3);
    int sub   = tid & 7;                       // feature octet
    bool valid = node < n;
    int vnode = valid ? node : n - 1;          // clamp: keep groups converged
    unsigned gmask = 0xFFu << (((tid >> 3) & 3) * 8);

    float acc[8] = {0.f, 0.f, 0.f, 0.f, 0.f, 0.f, 0.f, 0.f};
    const uint4* hrow = reinterpret_cast<const uint4*>(g_hh);
    int p    = g_off[vnode];
    int pend = g_off[vnode + 1];
    int deg  = pend - p;

    for (int base = 0; base < deg; base += 8) {
        int2 e = make_int2(0, 0);              // pad: src=0, w=+0.0f
        if (base + sub < deg) e = g_csr[p + base + sub];
#pragma unroll
        for (int j = 0; j < 8; j++) {
            int   src = __shfl_sync(gmask, e.x, j, 8);
            float w   = __int_as_float(__shfl_sync(gmask, e.y, j, 8));
            uint4 r   = hrow[(size_t)src * 8 + sub];
            fma8(acc, r, w);
        }
    }

    float s = 0.f, sq = 0.f;
    if (valid) {
        float di = g_dinv[node];
        float sn = di * di;                    // self-loop norm = 1/(deg+1)
        const float4 hs0 = *reinterpret_cast<const float4*>(
            g_h + (size_t)node * DD + sub * 8);
        const float4 hs1 = *reinterpret_cast<const float4*>(
            g_h + (size_t)node * DD + sub * 8 + 4);
        const float4 bv0 = *reinterpret_cast<const float4*>(b + sub * 8);
        const float4 bv1 = *reinterpret_cast<const float4*>(b + sub * 8 + 4);
        acc[0] += hs0.x * sn + bv0.x;
        acc[1] += hs0.y * sn + bv0.y;
        acc[2] += hs0.z * sn + bv0.z;
        acc[3] += hs0.w * sn + bv0.w;
        acc[4] += hs1.x * sn + bv1.x;
        acc[5] += hs1.y * sn + bv1.y;
        acc[6] += hs1.z * sn + bv1.z;
        acc[7] += hs1.w * sn + bv1.w;
        float4* orow = reinterpret_cast<float4*>(out + (size_t)node * DD + sub * 8);
        orow[0] = make_float4(acc[0], acc[1], acc[2], acc[3]);
        orow[1] = make_float4(acc[4], acc[5], acc[6], acc[7]);
#pragma unroll
        for (int i = 0; i < 8; i++) { s += acc[i]; sq += acc[i] * acc[i]; }
    }

    double ds = (double)s, dq = (double)sq;
#pragma unroll
    for (int o = 16; o; o >>= 1) {
        ds += __shfl_down_sync(0xffffffffu, ds, o);
        dq += __shfl_down_sync(0xffffffffu, dq, o);
    }
    __shared__ double sh[16];
    int w = tid >> 5, l = tid & 31;
    if (l == 0) { sh[w] = ds; sh[8 + w] = dq; }
    __syncthreads();
    if (tid == 0) {
        double S = 0.0, Q = 0.0;
#pragma unroll
        for (int i = 0; i < 8; i++) { S += sh[i]; Q += sh[8 + i]; }
        atomicAdd(&g_stats[0], S);
        atomicAdd(&g_stats[1], Q);
    }
}

// ---------------------------------------------------------------------------
// K5: graph layernorm (global mean/std) + affine + relu
// ---------------------------------------------------------------------------
__global__ void k_norm(float* __restrict__ out,
                       const float* __restrict__ lnw,
                       const float* __restrict__ lnb, int nq, int total) {
    int t = blockIdx.x * blockDim.x + threadIdx.x;
    if (t >= nq) return;
    double S = g_stats[0], Q = g_stats[1];
    double m = S / (double)total;
    float mean = (float)m;
    float var  = (float)(Q / (double)total - m * m);
    var = var > 0.f ? var : 0.f;
    float istd = 1.0f / (sqrtf(var) + LN_EPS);
    int seg = t & 15;
    float4 v = reinterpret_cast<float4*>(out)[t];
    const float4 wv = *reinterpret_cast<const float4*>(lnw + seg * 4);
    const float4 bv = *reinterpret_cast<const float4*>(lnb + seg * 4);
    v.x = fmaxf((v.x - mean) * istd * wv.x + bv.x, 0.f);
    v.y = fmaxf((v.y - mean) * istd * wv.y + bv.y, 0.f);
    v.z = fmaxf((v.z - mean) * istd * wv.z + bv.z, 0.f);
    v.w = fmaxf((v.w - mean) * istd * wv.w + bv.w, 0.f);
    reinterpret_cast<float4*>(out)[t] = v;
}

// ---------------------------------------------------------------------------
extern "C" void kernel_launch(void* const* d_in, const int* in_sizes, int n_in,
                              void* d_out, int out_size) {
    const float* x   = (const float*)d_in[0];
    const float* ew  = (const float*)d_in[1];
    const float* W   = (const float*)d_in[2];
    const float* b   = (const float*)d_in[3];
    const float* lnw = (const float*)d_in[4];
    const float* lnb = (const float*)d_in[5];
    const int*   ei  = (const int*)d_in[6];

    int N = in_sizes[0] / DD;
    int E = in_sizes[1];
    float* out = (float*)d_out;

    int gemm_blks  = (N + 31) / 32;
    int hist_blks  = (E + 255) / 256;
    int scan_tiles = (N + SCAN_TILE - 1) / SCAN_TILE;   // 13
    int dinv_blks  = (N + 1023) / 1024;                 // 49
    int nq = N * (DD / 4);
    int vec = ((E & 1) == 0) ? 1 : 0;
    int fill_items = vec ? (E + 1) / 2 : E;

    k_gemm_hist<<<gemm_blks + hist_blks + 1, 256>>>(x, W, ei, ew, N, E,
                                                    gemm_blks, hist_blks);
    k_scan_dinv<<<scan_tiles + dinv_blks, 1024>>>(N, scan_tiles);
    k_fill     <<<(fill_items + 255) / 256, 256>>>(ei, ew, E, vec);
    k_gather   <<<(N + 31) / 32, 256>>>(out, b, N);
    k_norm     <<<(nq + 255) / 256, 256>>>(out, lnw, lnb, nq, N * DD);
}